// round 5
// baseline (speedup 1.0000x reference)
#include <cuda_runtime.h>
#include <cuda_bf16.h>

#define OUT_CH 128
#define EPB 8          // edges per block (= warps per block: each warp writes one row)
#define THREADS 256

// Single fused kernel. Block b owns edges [b*EPB, (b+1)*EPB).
// 1) warp 0 finds the block's token range with one interleaved warp-parallel
//    lower_bound pair (segment_ids are globally sorted),
// 2) all 256 threads stream that range with coalesced int4 loads, predicating
//    each token by its segid, accumulating a packed-u64 smem histogram,
// 3) each warp writes one edge's 128-channel mean row (float4/lane, coalesced).
__global__ void __launch_bounds__(THREADS)
fused_edge_mean(const int* __restrict__ tokens,
                const int* __restrict__ segs,
                const float* __restrict__ emb,   // [4][128]
                float* __restrict__ out,         // [E][128]
                int total_tokens,
                int n_edges) {
    __shared__ unsigned long long s_hist[EPB];   // 16-bit field per token value
    __shared__ int s_range[2];

    const int tid  = threadIdx.x;
    const int lane = tid & 31;
    const int wid  = tid >> 5;
    const int e0   = blockIdx.x * EPB;

    if (tid < EPB) s_hist[tid] = 0ull;

    // ---- warp 0: interleaved warp-parallel lower_bound for e0 and e0+EPB ----
    if (wid == 0) {
        int lo0 = 0, hi0 = total_tokens;   // lower_bound(e0)
        int lo1 = 0, hi1 = total_tokens;   // lower_bound(e0+EPB)
        while ((hi0 > lo0) | (hi1 > lo1)) {
            int v0 = 0x7FFFFFFF, v1 = 0x7FFFFFFF;
            int step0 = 0, step1 = 0;
            if (hi0 > lo0) {
                step0 = (hi0 - lo0 + 31) >> 5;
                int idx = lo0 + lane * step0;
                if (idx < hi0) v0 = __ldg(&segs[idx]);
            }
            if (hi1 > lo1) {
                step1 = (hi1 - lo1 + 31) >> 5;
                int idx = lo1 + lane * step1;
                if (idx < hi1) v1 = __ldg(&segs[idx]);
            }
            if (hi0 > lo0) {
                unsigned m = __ballot_sync(0xFFFFFFFFu, v0 < e0);
                int cnt = __popc(m);
                int nlo = cnt ? lo0 + (cnt - 1) * step0 + 1 : lo0;
                int nhi = (cnt < 32) ? min(hi0, lo0 + cnt * step0) : hi0;
                lo0 = nlo; hi0 = max(nhi, nlo);
            }
            if (hi1 > lo1) {
                unsigned m = __ballot_sync(0xFFFFFFFFu, v1 < e0 + EPB);
                int cnt = __popc(m);
                int nlo = cnt ? lo1 + (cnt - 1) * step1 + 1 : lo1;
                int nhi = (cnt < 32) ? min(hi1, lo1 + cnt * step1) : hi1;
                lo1 = nlo; hi1 = max(nhi, nlo);
            }
        }
        if (lane == 0) { s_range[0] = lo0; s_range[1] = lo1; }
    }
    __syncthreads();

    const int start = s_range[0];
    const int end   = s_range[1];

    // ---- coalesced int4 streaming with segid predication ----
    const int4* tokens4 = (const int4*)tokens;
    const int4* segs4   = (const int4*)segs;
    const int s4 = start >> 2;
    const int e4 = (end + 3) >> 2;          // <= total_tokens/4 since end <= total

    for (int j = s4 + tid; j < e4; j += THREADS) {
        const int4 t = tokens4[j];
        const int4 s = segs4[j];
        if (s.x == s.w) {                    // sorted -> whole group same segment
            const int le = s.x - e0;
            if ((unsigned)le < EPB) {
                unsigned long long a = (1ull << (t.x * 16)) + (1ull << (t.y * 16))
                                     + (1ull << (t.z * 16)) + (1ull << (t.w * 16));
                atomicAdd(&s_hist[le], a);
            }
        } else {                             // rare: segment boundary inside group
            const int ss[4] = {s.x, s.y, s.z, s.w};
            const int tt[4] = {t.x, t.y, t.z, t.w};
#pragma unroll
            for (int k = 0; k < 4; k++) {
                const int le = ss[k] - e0;
                if ((unsigned)le < EPB)
                    atomicAdd(&s_hist[le], 1ull << (tt[k] * 16));
            }
        }
    }
    __syncthreads();

    // ---- epilogue: warp w writes edge e0+w ----
    const int e = e0 + wid;
    if (e < n_edges) {
        const unsigned long long h = s_hist[wid];
        const float f0 = (float)((unsigned)(h      ) & 0xFFFFu);
        const float f1 = (float)((unsigned)(h >> 16) & 0xFFFFu);
        const float f2 = (float)((unsigned)(h >> 32) & 0xFFFFu);
        const float f3 = (float)((unsigned)(h >> 48) & 0xFFFFu);
        const float inv = 1.0f / fmaxf(f0 + f1 + f2 + f3, 1.0f);

        const int d = lane * 4;
        const float4 e0v = *(const float4*)(emb + 0 * OUT_CH + d);
        const float4 e1v = *(const float4*)(emb + 1 * OUT_CH + d);
        const float4 e2v = *(const float4*)(emb + 2 * OUT_CH + d);
        const float4 e3v = *(const float4*)(emb + 3 * OUT_CH + d);

        float4 r;
        r.x = (f0 * e0v.x + f1 * e1v.x + f2 * e2v.x + f3 * e3v.x) * inv;
        r.y = (f0 * e0v.y + f1 * e1v.y + f2 * e2v.y + f3 * e3v.y) * inv;
        r.z = (f0 * e0v.z + f1 * e1v.z + f2 * e2v.z + f3 * e3v.z) * inv;
        r.w = (f0 * e0v.w + f1 * e1v.w + f2 * e2v.w + f3 * e3v.w) * inv;

        *(float4*)(out + (long long)e * OUT_CH + d) = r;
    }
}

extern "C" void kernel_launch(void* const* d_in, const int* in_sizes, int n_in,
                              void* d_out, int out_size) {
    // Inputs: 0 overlap_similarity f32[E], 1 overlap_length f32[E],
    //         2 tokens i32[T], 3 segment_ids i32[T], 4 embedding f32[4*128],
    //         5 n_edges
    const int*   tokens = (const int*)d_in[2];
    const int*   segs   = (const int*)d_in[3];
    const float* emb    = (const float*)d_in[4];
    float*       out    = (float*)d_out;

    const int total_tokens = in_sizes[2];
    const int n_edges      = out_size / OUT_CH;

    const int blocks = (n_edges + EPB - 1) / EPB;   // 1024
    fused_edge_mean<<<blocks, THREADS>>>(tokens, segs, emb, out,
                                         total_tokens, n_edges);
}

// round 6
// speedup vs baseline: 2.1866x; 2.1866x over previous
#include <cuda_runtime.h>
#include <cuda_bf16.h>

#define OUT_CH  128
#define EPB     8            // edges per block
#define THREADS 256
#define NW      (THREADS/32) // 8 warps

// Single fused kernel. Block b owns edges [b*EPB, (b+1)*EPB).
//  - warps 0/1 each run one warp-parallel lower_bound (block range bounds)
//  - all threads stream the range with coalesced int4 loads, accumulating
//    into PRIVATE smem slots s_acc[warp][edge][lane]  (no atomics at all)
//  - warp w reduces + writes edge e0+w's 128-channel mean row
__global__ void __launch_bounds__(THREADS)
fused_edge_mean(const int* __restrict__ tokens,
                const int* __restrict__ segs,
                const float* __restrict__ emb,   // [4][128]
                float* __restrict__ out,         // [E][128]
                int total_tokens,
                int n_edges) {
    // Packed histogram: count of token t in 16-bit field t of a u64.
    __shared__ unsigned long long s_acc[NW][EPB][32];   // 16 KB
    __shared__ int s_range[2];

    const int tid  = threadIdx.x;
    const int lane = tid & 31;
    const int wid  = tid >> 5;
    const int e0   = blockIdx.x * EPB;

    // zero private slots (each thread zeroes its own 8)
#pragma unroll
    for (int k = 0; k < EPB; k++) s_acc[wid][k][lane] = 0ull;

    // ---- warps 0 and 1: warp-parallel lower_bound for e0 / e0+EPB ----
    if (wid < 2) {
        const int target = (wid == 0) ? e0 : e0 + EPB;
        int lo = 0, hi = total_tokens;
        while (hi > lo) {
            const int step = (hi - lo + 31) >> 5;      // ceil(range/32)
            const int idx  = lo + lane * step;
            int v = 0x7FFFFFFF;
            if (idx < hi) v = __ldg(&segs[idx]);
            const unsigned m = __ballot_sync(0xFFFFFFFFu, v < target);
            const int cnt = __popc(m);                 // sorted -> contiguous mask
            const int nlo = cnt ? lo + (cnt - 1) * step + 1 : lo;
            const int nhi = (cnt < 32) ? min(hi, lo + cnt * step) : hi;
            lo = nlo; hi = max(nhi, nlo);
        }
        if (lane == 0) s_range[wid] = lo;
    }
    __syncthreads();

    const int start = s_range[0];
    const int end   = s_range[1];

    // ---- coalesced int4 streaming, conflict-free private accumulation ----
    const int4* tokens4 = (const int4*)tokens;
    const int4* segs4   = (const int4*)segs;
    const int s4 = start >> 2;
    const int e4 = (end + 3) >> 2;

    for (int j = s4 + tid; j < e4; j += THREADS) {
        const int4 t = tokens4[j];
        const int4 s = segs4[j];
        if (s.x == s.w) {                    // sorted -> whole group one segment
            const int le = s.x - e0;
            if ((unsigned)le < EPB) {
                const unsigned long long a =
                      (1ull << (t.x * 16)) + (1ull << (t.y * 16))
                    + (1ull << (t.z * 16)) + (1ull << (t.w * 16));
                s_acc[wid][le][lane] += a;   // plain LDS+ADD+STS, own slot
            }
        } else {                             // rare: segment boundary in group
            const int ss[4] = {s.x, s.y, s.z, s.w};
            const int tt[4] = {t.x, t.y, t.z, t.w};
#pragma unroll
            for (int k = 0; k < 4; k++) {
                const int le = ss[k] - e0;
                if ((unsigned)le < EPB)
                    s_acc[wid][le][lane] += 1ull << (tt[k] * 16);
            }
        }
    }
    __syncthreads();

    // ---- epilogue: warp w reduces + writes edge e0+w ----
    const int e = e0 + wid;
    if (e < n_edges) {
        unsigned long long sum = 0ull;
#pragma unroll
        for (int w = 0; w < NW; w++) sum += s_acc[w][wid][lane];

        // per-field totals << 65536: the two 32-bit halves reduce carry-free
        const unsigned lo32 = __reduce_add_sync(0xFFFFFFFFu, (unsigned)sum);
        const unsigned hi32 = __reduce_add_sync(0xFFFFFFFFu, (unsigned)(sum >> 32));

        const float f0 = (float)(lo32 & 0xFFFFu);
        const float f1 = (float)(lo32 >> 16);
        const float f2 = (float)(hi32 & 0xFFFFu);
        const float f3 = (float)(hi32 >> 16);
        const float inv = 1.0f / fmaxf(f0 + f1 + f2 + f3, 1.0f);

        const int d = lane * 4;
        const float4 e0v = *(const float4*)(emb + 0 * OUT_CH + d);
        const float4 e1v = *(const float4*)(emb + 1 * OUT_CH + d);
        const float4 e2v = *(const float4*)(emb + 2 * OUT_CH + d);
        const float4 e3v = *(const float4*)(emb + 3 * OUT_CH + d);

        float4 r;
        r.x = (f0 * e0v.x + f1 * e1v.x + f2 * e2v.x + f3 * e3v.x) * inv;
        r.y = (f0 * e0v.y + f1 * e1v.y + f2 * e2v.y + f3 * e3v.y) * inv;
        r.z = (f0 * e0v.z + f1 * e1v.z + f2 * e2v.z + f3 * e3v.z) * inv;
        r.w = (f0 * e0v.w + f1 * e1v.w + f2 * e2v.w + f3 * e3v.w) * inv;

        *(float4*)(out + (long long)e * OUT_CH + d) = r;
    }
}

extern "C" void kernel_launch(void* const* d_in, const int* in_sizes, int n_in,
                              void* d_out, int out_size) {
    // Inputs: 0 overlap_similarity f32[E], 1 overlap_length f32[E],
    //         2 tokens i32[T], 3 segment_ids i32[T], 4 embedding f32[4*128],
    //         5 n_edges
    const int*   tokens = (const int*)d_in[2];
    const int*   segs   = (const int*)d_in[3];
    const float* emb    = (const float*)d_in[4];
    float*       out    = (float*)d_out;

    const int total_tokens = in_sizes[2];
    const int n_edges      = out_size / OUT_CH;

    const int blocks = (n_edges + EPB - 1) / EPB;   // 1024
    fused_edge_mean<<<blocks, THREADS>>>(tokens, segs, emb, out,
                                         total_tokens, n_edges);
}